// round 3
// baseline (speedup 1.0000x reference)
#include <cuda_runtime.h>
#include <math.h>

#define BATCH   4
#define TQ      2048
#define TK      2048
#define DMODEL  1024
#define NHEADS  16
#define HDIM    64
#define MROWS   (BATCH * TQ)   // 8192

// ---------------- scratch (allocation-free rule: __device__ globals) -------
__device__ float g_Q[MROWS * DMODEL];  // (b,h,t,hd)  tf32-rounded, pre-scaled
__device__ float g_K[MROWS * DMODEL];  // (b,h,t,hd)  tf32-rounded
__device__ float g_V[MROWS * DMODEL];  // (b,h,t,hd)  tf32-rounded
__device__ float g_O[MROWS * DMODEL];  // (b,t,dmodel) fp32

// ---------------- helpers ---------------------------------------------------
__device__ __forceinline__ unsigned f2tf(float x) {
    unsigned r;
    asm("cvt.rna.tf32.f32 %0, %1;" : "=r"(r) : "f"(x));
    return r;
}

__device__ __forceinline__ void mma_tf32(float* d, const unsigned* a, const unsigned* b) {
    asm volatile(
        "mma.sync.aligned.m16n8k8.row.col.f32.tf32.tf32.f32 "
        "{%0,%1,%2,%3}, {%4,%5,%6,%7}, {%8,%9}, {%0,%1,%2,%3};"
        : "+f"(d[0]), "+f"(d[1]), "+f"(d[2]), "+f"(d[3])
        : "r"(a[0]), "r"(a[1]), "r"(a[2]), "r"(a[3]), "r"(b[0]), "r"(b[1]));
}

__device__ __forceinline__ void cp16(void* smem_dst, const void* gmem_src) {
    unsigned s = (unsigned)__cvta_generic_to_shared(smem_dst);
    asm volatile("cp.async.cg.shared.global [%0], [%1], 16;" :: "r"(s), "l"(gmem_src));
}

// ---------------- tf32 GEMM: C = A(M,K) @ W(N,K)^T --------------------------
// 128x128x32 block, 4 warps of 64x64, 128 threads, cp.async double buffer.
// MODE 0: plain fp32 output (row-major M x N)
// MODE 1: split-heads output, tf32-rounded, scaled
#define BM   128
#define BN   128
#define BK   32
#define SSTR 36

template <int MODE>
__global__ void __launch_bounds__(128, 2)
gemm_tf32(const float* __restrict__ A, const float* __restrict__ W,
          float* __restrict__ C, float scale)
{
    extern __shared__ float sm[];
    float* As = sm;                       // [2][BM][SSTR]
    float* Ws = sm + 2 * BM * SSTR;       // [2][BN][SSTR]

    const int tid  = threadIdx.x;
    const int lane = tid & 31;
    const int warp = tid >> 5;            // 0..3
    const int wm   = warp >> 1;           // 0..1  (64 rows)
    const int wn   = warp & 1;            // 0..1  (64 cols)
    const int bm   = blockIdx.y * BM;
    const int bn   = blockIdx.x * BN;
    const int lr   = lane >> 2;
    const int lc   = lane & 3;

    float acc[4][8][4];
#pragma unroll
    for (int i = 0; i < 4; i++)
#pragma unroll
        for (int j = 0; j < 8; j++)
#pragma unroll
            for (int c = 0; c < 4; c++) acc[i][j][c] = 0.f;

    const int NIT = DMODEL / BK;  // 32

    auto load_stage = [&](int st, int k0) {
#pragma unroll
        for (int r = 0; r < 8; r++) {
            int id = tid + r * 128;
            int m  = id >> 3;
            int k4 = (id & 7) * 4;
            cp16(&As[(st * BM + m) * SSTR + k4], &A[(size_t)(bm + m) * DMODEL + k0 + k4]);
        }
#pragma unroll
        for (int r = 0; r < 8; r++) {
            int id = tid + r * 128;
            int m  = id >> 3;
            int k4 = (id & 7) * 4;
            cp16(&Ws[(st * BN + m) * SSTR + k4], &W[(size_t)(bn + m) * DMODEL + k0 + k4]);
        }
        asm volatile("cp.async.commit_group;");
    };

    load_stage(0, 0);

    for (int it = 0; it < NIT; it++) {
        if (it + 1 < NIT) {
            load_stage((it + 1) & 1, (it + 1) * BK);
            asm volatile("cp.async.wait_group 1;");
        } else {
            asm volatile("cp.async.wait_group 0;");
        }
        __syncthreads();
        const float* Ab = &As[(it & 1) * BM * SSTR];
        const float* Wb = &Ws[(it & 1) * BN * SSTR];

#pragma unroll
        for (int kk = 0; kk < 4; kk++) {
            const int k = kk * 8;
            unsigned af[4][4], bf[8][2];
#pragma unroll
            for (int mf = 0; mf < 4; mf++) {
                const float* p = &Ab[(wm * 64 + mf * 16 + lr) * SSTR + k + lc];
                af[mf][0] = f2tf(p[0]);
                af[mf][1] = f2tf(p[8 * SSTR]);
                af[mf][2] = f2tf(p[4]);
                af[mf][3] = f2tf(p[8 * SSTR + 4]);
            }
#pragma unroll
            for (int nf = 0; nf < 8; nf++) {
                const float* p = &Wb[(wn * 64 + nf * 8 + lr) * SSTR + k + lc];
                bf[nf][0] = f2tf(p[0]);
                bf[nf][1] = f2tf(p[4]);
            }
#pragma unroll
            for (int mf = 0; mf < 4; mf++)
#pragma unroll
                for (int nf = 0; nf < 8; nf++)
                    mma_tf32(acc[mf][nf], af[mf], bf[nf]);
        }
        __syncthreads();
    }

    // epilogue
#pragma unroll
    for (int mf = 0; mf < 4; mf++) {
#pragma unroll
        for (int half = 0; half < 2; half++) {
            const int m = bm + wm * 64 + mf * 16 + lr + half * 8;
#pragma unroll
            for (int nf = 0; nf < 8; nf++) {
                const int n = bn + wn * 64 + nf * 8 + 2 * lc;
                float2 v = make_float2(acc[mf][nf][half * 2], acc[mf][nf][half * 2 + 1]);
                if (MODE == 0) {
                    *(float2*)&C[(size_t)m * DMODEL + n] = v;
                } else {
                    v.x = __uint_as_float(f2tf(v.x * scale));
                    v.y = __uint_as_float(f2tf(v.y * scale));
                    const int b = m >> 11, t = m & 2047;   // TQ = 2048
                    const int h = n >> 6,  hd = n & 63;    // HDIM = 64
                    *(float2*)&C[(((size_t)(b * NHEADS + h) * TQ + t) << 6) + hd] = v;
                }
            }
        }
    }
}

// ---------------- fused attention, tf32 mma ----------------------------------
// q-block 128 rows, 4 warps, 32 rows per warp (2 m16 tiles); K tile 64 keys;
// cp.async double-buffered K/V (pre-converted tf32); Q smem reused for P.
#define AQ   128
#define KT   64
#define QSTR 68   // 68 % 32 == 4
#define VSTR 72   // 72 % 32 == 8

__global__ void __launch_bounds__(128, 2)
attn_tf32(const float* __restrict__ Q, const float* __restrict__ K,
          const float* __restrict__ V, const float* __restrict__ mask,
          const unsigned char* __restrict__ kpm, float* __restrict__ O)
{
    extern __shared__ float sm[];
    float* Ps = sm;                         // 128 x 68 (Q staging, then P)
    float* Ks = sm + AQ * QSTR;             // [2][64][68]
    float* Vs = Ks + 2 * KT * QSTR;         // [2][64][72]

    const int tid  = threadIdx.x;
    const int lane = tid & 31;
    const int warp = tid >> 5;
    const int lr   = lane >> 2;
    const int lc   = lane & 3;

    const int q0 = blockIdx.x * AQ;
    const int bh = blockIdx.y;
    const int b  = bh >> 4;
    const int h  = bh & 15;

    const float* Qb = Q + (size_t)bh * TQ * HDIM;
    const float* Kb = K + (size_t)bh * TK * HDIM;
    const float* Vb = V + (size_t)bh * TK * HDIM;

    // stage Q tile (raw copy — already tf32 bits, pre-scaled)
#pragma unroll
    for (int r = 0; r < 16; r++) {
        int id  = tid + r * 128;            // 2048 float4 slots: 128 rows x 16
        int row = id >> 4, c4 = (id & 15) * 4;
        *(float4*)&Ps[row * QSTR + c4] = *(const float4*)&Qb[(size_t)(q0 + row) * HDIM + c4];
    }
    __syncthreads();

    // hoist Q fragments: 2 m-tiles x 8 k-steps
    unsigned qf[2][8][4];
#pragma unroll
    for (int mt = 0; mt < 2; mt++)
#pragma unroll
        for (int kk = 0; kk < 8; kk++) {
            const float* p = &Ps[(warp * 32 + mt * 16 + lr) * QSTR + kk * 8 + lc];
            qf[mt][kk][0] = __float_as_uint(p[0]);
            qf[mt][kk][1] = __float_as_uint(p[8 * QSTR]);
            qf[mt][kk][2] = __float_as_uint(p[4]);
            qf[mt][kk][3] = __float_as_uint(p[8 * QSTR + 4]);
        }
    __syncthreads();   // all qf hoisted before Ps becomes P scratch

    float m_i[2][2], l_i[2][2], o[2][8][4];
#pragma unroll
    for (int mt = 0; mt < 2; mt++) {
#pragma unroll
        for (int half = 0; half < 2; half++) { m_i[mt][half] = -INFINITY; l_i[mt][half] = 0.f; }
#pragma unroll
        for (int nf = 0; nf < 8; nf++)
#pragma unroll
            for (int c = 0; c < 4; c++) o[mt][nf][c] = 0.f;
    }

    auto load_kv = [&](int st, int kt) {
        const int k0 = kt * KT;
#pragma unroll
        for (int r = 0; r < 8; r++) {
            int id  = tid + r * 128;        // 1024 slots: 64 rows x 16
            int row = id >> 4, c4 = (id & 15) * 4;
            cp16(&Ks[st * KT * QSTR + row * QSTR + c4],
                 &Kb[(size_t)(k0 + row) * HDIM + c4]);
        }
#pragma unroll
        for (int r = 0; r < 8; r++) {
            int id  = tid + r * 128;
            int row = id >> 4, c4 = (id & 15) * 4;
            cp16(&Vs[st * KT * VSTR + row * VSTR + c4],
                 &Vb[(size_t)(k0 + row) * HDIM + c4]);
        }
        asm volatile("cp.async.commit_group;");
    };

    load_kv(0, 0);

    const int NT = TK / KT;   // 32
    for (int kt = 0; kt < NT; kt++) {
        if (kt + 1 < NT) {
            load_kv((kt + 1) & 1, kt + 1);
            asm volatile("cp.async.wait_group 1;");
        } else {
            asm volatile("cp.async.wait_group 0;");
        }
        __syncthreads();
        const float* Kst = &Ks[(kt & 1) * KT * QSTR];
        const float* Vst = &Vs[(kt & 1) * KT * VSTR];
        const int k0 = kt * KT;

        // S = Q @ K^T for both m-tiles (B-fragment reused across m-tiles)
        float s[2][8][4];
#pragma unroll
        for (int mt = 0; mt < 2; mt++)
#pragma unroll
            for (int nf = 0; nf < 8; nf++)
#pragma unroll
                for (int c = 0; c < 4; c++) s[mt][nf][c] = 0.f;

#pragma unroll
        for (int kk = 0; kk < 8; kk++) {
#pragma unroll
            for (int nf = 0; nf < 8; nf++) {
                unsigned bf[2];
                const float* p = &Kst[(nf * 8 + lr) * QSTR + kk * 8 + lc];
                bf[0] = __float_as_uint(p[0]);
                bf[1] = __float_as_uint(p[4]);
                mma_tf32(s[0][nf], qf[0][kk], bf);
                mma_tf32(s[1][nf], qf[1][kk], bf);
            }
        }

        // key padding flags (shared by all rows this tile)
        uchar2 kp[8];
#pragma unroll
        for (int nf = 0; nf < 8; nf++)
            kp[nf] = *(const uchar2*)&kpm[(size_t)b * TK + k0 + nf * 8 + 2 * lc];

        // masks + online softmax
#pragma unroll
        for (int mt = 0; mt < 2; mt++) {
#pragma unroll
            for (int half = 0; half < 2; half++) {
                const int qg = q0 + warp * 32 + mt * 16 + lr + half * 8;
                const float* mrow = &mask[(size_t)qg * TK + k0];
                float mx = -INFINITY;
#pragma unroll
                for (int nf = 0; nf < 8; nf++) {
                    float2 mv = *(const float2*)&mrow[nf * 8 + 2 * lc];
                    float v0 = s[mt][nf][half * 2]     + mv.x;
                    float v1 = s[mt][nf][half * 2 + 1] + mv.y;
                    if (kp[nf].x) v0 = -INFINITY;
                    if (kp[nf].y) v1 = -INFINITY;
                    s[mt][nf][half * 2]     = v0;
                    s[mt][nf][half * 2 + 1] = v1;
                    mx = fmaxf(mx, fmaxf(v0, v1));
                }
                mx = fmaxf(mx, __shfl_xor_sync(0xffffffffu, mx, 1));
                mx = fmaxf(mx, __shfl_xor_sync(0xffffffffu, mx, 2));
                float mnew = fmaxf(m_i[mt][half], mx);
                float alpha, rs = 0.f;
                if (mnew == -INFINITY) {
                    alpha = 1.f;
#pragma unroll
                    for (int nf = 0; nf < 8; nf++) {
                        s[mt][nf][half * 2] = 0.f;
                        s[mt][nf][half * 2 + 1] = 0.f;
                    }
                } else {
                    alpha = (m_i[mt][half] == -INFINITY) ? 0.f : __expf(m_i[mt][half] - mnew);
#pragma unroll
                    for (int nf = 0; nf < 8; nf++) {
                        float p0 = __expf(s[mt][nf][half * 2]     - mnew);
                        float p1 = __expf(s[mt][nf][half * 2 + 1] - mnew);
                        s[mt][nf][half * 2]     = p0;
                        s[mt][nf][half * 2 + 1] = p1;
                        rs += p0 + p1;
                    }
                }
                rs += __shfl_xor_sync(0xffffffffu, rs, 1);
                rs += __shfl_xor_sync(0xffffffffu, rs, 2);
                l_i[mt][half] = l_i[mt][half] * alpha + rs;
                m_i[mt][half] = mnew;
#pragma unroll
                for (int nf = 0; nf < 8; nf++) {
                    o[mt][nf][half * 2]     *= alpha;
                    o[mt][nf][half * 2 + 1] *= alpha;
                }
            }
        }

        // stage P (tf32 bits) into warp-private rows of Ps
#pragma unroll
        for (int mt = 0; mt < 2; mt++)
#pragma unroll
            for (int half = 0; half < 2; half++) {
                const int row = warp * 32 + mt * 16 + lr + half * 8;
#pragma unroll
                for (int nf = 0; nf < 8; nf++) {
                    float2 pv;
                    pv.x = __uint_as_float(f2tf(s[mt][nf][half * 2]));
                    pv.y = __uint_as_float(f2tf(s[mt][nf][half * 2 + 1]));
                    *(float2*)&Ps[row * QSTR + nf * 8 + 2 * lc] = pv;
                }
            }
        __syncwarp();

        // O += P @ V  (V-fragment reused across m-tiles)
#pragma unroll
        for (int kk = 0; kk < 8; kk++) {
            unsigned af[2][4];
#pragma unroll
            for (int mt = 0; mt < 2; mt++) {
                const float* pa = &Ps[(warp * 32 + mt * 16 + lr) * QSTR + kk * 8 + lc];
                af[mt][0] = __float_as_uint(pa[0]);
                af[mt][1] = __float_as_uint(pa[8 * QSTR]);
                af[mt][2] = __float_as_uint(pa[4]);
                af[mt][3] = __float_as_uint(pa[8 * QSTR + 4]);
            }
#pragma unroll
            for (int nf = 0; nf < 8; nf++) {
                unsigned bf[2];
                const float* pb = &Vst[(kk * 8 + lc) * VSTR + nf * 8 + lr];
                bf[0] = __float_as_uint(pb[0]);
                bf[1] = __float_as_uint(pb[4 * VSTR]);
                mma_tf32(o[0][nf], af[0], bf);
                mma_tf32(o[1][nf], af[1], bf);
            }
        }
        __syncthreads();   // consumers done before stage is overwritten
    }

    // finalize: (b, t, dmodel) layout
#pragma unroll
    for (int mt = 0; mt < 2; mt++)
#pragma unroll
        for (int half = 0; half < 2; half++) {
            const float inv = (l_i[mt][half] > 0.f) ? (1.f / l_i[mt][half]) : 0.f;
            const int t = q0 + warp * 32 + mt * 16 + lr + half * 8;
#pragma unroll
            for (int nf = 0; nf < 8; nf++) {
                float2 v = make_float2(o[mt][nf][half * 2] * inv,
                                       o[mt][nf][half * 2 + 1] * inv);
                *(float2*)&O[((size_t)(b * TQ + t)) * DMODEL + h * HDIM + nf * 8 + 2 * lc] = v;
            }
        }
}

// ---------------- launch ------------------------------------------------------
extern "C" void kernel_launch(void* const* d_in, const int* in_sizes, int n_in,
                              void* d_out, int out_size)
{
    const float* x_q   = (const float*)d_in[0];
    const float* x_kv  = (const float*)d_in[1];
    const float* amask = (const float*)d_in[2];
    const unsigned char* kpm = (const unsigned char*)d_in[3];
    const float* Wq = (const float*)d_in[4];
    const float* Wk = (const float*)d_in[5];
    const float* Wv = (const float*)d_in[6];
    const float* Wo = (const float*)d_in[7];
    float* out = (float*)d_out;

    float *qP, *kP, *vP, *oP;
    cudaGetSymbolAddress((void**)&qP, g_Q);
    cudaGetSymbolAddress((void**)&kP, g_K);
    cudaGetSymbolAddress((void**)&vP, g_V);
    cudaGetSymbolAddress((void**)&oP, g_O);

    const int gemm_smem = 2 * (BM + BN) * SSTR * (int)sizeof(float);   // 73728
    cudaFuncSetAttribute(gemm_tf32<0>, cudaFuncAttributeMaxDynamicSharedMemorySize, gemm_smem);
    cudaFuncSetAttribute(gemm_tf32<1>, cudaFuncAttributeMaxDynamicSharedMemorySize, gemm_smem);

    dim3 gblk(DMODEL / BN, MROWS / BM);   // (8, 64)
    gemm_tf32<1><<<gblk, 128, gemm_smem>>>(x_q,  Wq, qP, 0.125f);
    gemm_tf32<1><<<gblk, 128, gemm_smem>>>(x_kv, Wk, kP, 1.0f);
    gemm_tf32<1><<<gblk, 128, gemm_smem>>>(x_kv, Wv, vP, 1.0f);

    const int attn_smem = (AQ * QSTR + 2 * KT * QSTR + 2 * KT * VSTR) * (int)sizeof(float); // 106496
    cudaFuncSetAttribute(attn_tf32, cudaFuncAttributeMaxDynamicSharedMemorySize, attn_smem);
    dim3 ga(TQ / AQ, BATCH * NHEADS);     // (16, 64)
    attn_tf32<<<ga, 128, attn_smem>>>(qP, kP, vP, amask, kpm, oP);

    gemm_tf32<0><<<gblk, 128, gemm_smem>>>(oP, Wo, out, 1.0f);
}

// round 4
// speedup vs baseline: 1.2082x; 1.2082x over previous
#include <cuda_runtime.h>
#include <math.h>

#define BATCH   4
#define TQ      2048
#define TK      2048
#define DMODEL  1024
#define NHEADS  16
#define HDIM    64
#define MROWS   (BATCH * TQ)   // 8192

// ---------------- scratch (allocation-free rule: __device__ globals) -------
__device__ float g_Q[MROWS * DMODEL];  // (b,h,t,hd)  tf32 bits, pre-scaled 1/8
__device__ float g_K[MROWS * DMODEL];  // (b,h,t,hd)  tf32 bits
__device__ float g_V[MROWS * DMODEL];  // (b,h,t,hd)  tf32 bits
__device__ float g_O[MROWS * DMODEL];  // (b,t,dmodel) fp32

// ---------------- helpers ---------------------------------------------------
__device__ __forceinline__ unsigned f2tf(float x) {
    unsigned r;
    asm("cvt.rna.tf32.f32 %0, %1;" : "=r"(r) : "f"(x));
    return r;
}

__device__ __forceinline__ void mma_tf32(float* d, const unsigned* a, const unsigned* b) {
    asm volatile(
        "mma.sync.aligned.m16n8k8.row.col.f32.tf32.tf32.f32 "
        "{%0,%1,%2,%3}, {%4,%5,%6,%7}, {%8,%9}, {%0,%1,%2,%3};"
        : "+f"(d[0]), "+f"(d[1]), "+f"(d[2]), "+f"(d[3])
        : "r"(a[0]), "r"(a[1]), "r"(a[2]), "r"(a[3]), "r"(b[0]), "r"(b[1]));
}

__device__ __forceinline__ void cp16(void* smem_dst, const void* gmem_src) {
    unsigned s = (unsigned)__cvta_generic_to_shared(smem_dst);
    asm volatile("cp.async.cg.shared.global [%0], [%1], 16;" :: "r"(s), "l"(gmem_src));
}

// ---------------- tf32 GEMM: C = A(M,K) @ W(N,K)^T --------------------------
// 128x128x32 block, 256 threads, 8 warps of 64x32, cp.async double buffer.
// MODE 0: plain fp32 output (row-major MxN); MODE 1: split-heads tf32+scale.
#define BM   128
#define BN   128
#define BK   32
#define SSTR 36

template <int MODE>
__global__ void __launch_bounds__(256, 2)
gemm_tf32(const float* __restrict__ A, const float* __restrict__ W,
          float* __restrict__ C, float scale)
{
    extern __shared__ float sm[];
    float* As = sm;                       // [2][BM][SSTR]
    float* Ws = sm + 2 * BM * SSTR;       // [2][BN][SSTR]

    const int tid  = threadIdx.x;
    const int lane = tid & 31;
    const int warp = tid >> 5;
    const int wm   = warp >> 2;           // 0..1
    const int wn   = warp & 3;            // 0..3
    const int bm   = blockIdx.y * BM;
    const int bn   = blockIdx.x * BN;
    const int lr   = lane >> 2;
    const int lc   = lane & 3;

    float acc[4][4][4];
#pragma unroll
    for (int i = 0; i < 4; i++)
#pragma unroll
        for (int j = 0; j < 4; j++)
#pragma unroll
            for (int c = 0; c < 4; c++) acc[i][j][c] = 0.f;

    const int NIT = DMODEL / BK;  // 32

    auto load_stage = [&](int st, int k0) {
#pragma unroll
        for (int r = 0; r < 4; r++) {
            int id = tid + r * 256;
            int m  = id >> 3;
            int k4 = (id & 7) * 4;
            cp16(&As[(st * BM + m) * SSTR + k4], &A[(size_t)(bm + m) * DMODEL + k0 + k4]);
            cp16(&Ws[(st * BN + m) * SSTR + k4], &W[(size_t)(bn + m) * DMODEL + k0 + k4]);
        }
        asm volatile("cp.async.commit_group;");
    };

    load_stage(0, 0);

    for (int it = 0; it < NIT; it++) {
        if (it + 1 < NIT) {
            load_stage((it + 1) & 1, (it + 1) * BK);
            asm volatile("cp.async.wait_group 1;");
        } else {
            asm volatile("cp.async.wait_group 0;");
        }
        __syncthreads();
        const float* Ab = &As[(it & 1) * BM * SSTR];
        const float* Wb = &Ws[(it & 1) * BN * SSTR];

#pragma unroll
        for (int kk = 0; kk < 4; kk++) {
            const int k = kk * 8;
            unsigned af[4][4], bf[4][2];
#pragma unroll
            for (int mf = 0; mf < 4; mf++) {
                const float* p = &Ab[(wm * 64 + mf * 16 + lr) * SSTR + k + lc];
                af[mf][0] = f2tf(p[0]);
                af[mf][1] = f2tf(p[8 * SSTR]);
                af[mf][2] = f2tf(p[4]);
                af[mf][3] = f2tf(p[8 * SSTR + 4]);
            }
#pragma unroll
            for (int nf = 0; nf < 4; nf++) {
                const float* p = &Wb[(wn * 32 + nf * 8 + lr) * SSTR + k + lc];
                bf[nf][0] = f2tf(p[0]);
                bf[nf][1] = f2tf(p[4]);
            }
#pragma unroll
            for (int mf = 0; mf < 4; mf++)
#pragma unroll
                for (int nf = 0; nf < 4; nf++)
                    mma_tf32(acc[mf][nf], af[mf], bf[nf]);
        }
        __syncthreads();
    }

    // epilogue
#pragma unroll
    for (int mf = 0; mf < 4; mf++) {
#pragma unroll
        for (int half = 0; half < 2; half++) {
            const int m = bm + wm * 64 + mf * 16 + lr + half * 8;
#pragma unroll
            for (int nf = 0; nf < 4; nf++) {
                const int n = bn + wn * 32 + nf * 8 + 2 * lc;
                float2 v = make_float2(acc[mf][nf][half * 2], acc[mf][nf][half * 2 + 1]);
                if (MODE == 0) {
                    *(float2*)&C[(size_t)m * DMODEL + n] = v;
                } else {
                    v.x = __uint_as_float(f2tf(v.x * scale));
                    v.y = __uint_as_float(f2tf(v.y * scale));
                    const int b = m >> 11, t = m & 2047;   // TQ = 2048
                    const int h = n >> 6,  hd = n & 63;    // HDIM = 64
                    *(float2*)&C[(((size_t)(b * NHEADS + h) * TQ + t) << 6) + hd] = v;
                }
            }
        }
    }
}

// ---------------- fused attention, tf32 mma ----------------------------------
// 64 q-rows, 4 warps (16 rows each); KT=64 keys; K double-buffered via cp.async,
// V single-buffered with copy overlapped against QK+softmax. Q/K/V already tf32.
#define AQ   64
#define KT   64
#define KSTR 68   // 68 % 32 == 4
#define VSTR 72   // 72 % 32 == 8

__global__ void __launch_bounds__(128, 3)
attn_tf32(const float* __restrict__ Q, const float* __restrict__ K,
          const float* __restrict__ V, const float* __restrict__ mask,
          const unsigned char* __restrict__ kpm, float* __restrict__ O)
{
    extern __shared__ float sm[];
    float* QPs = sm;                        // 64 x 68 (Q staging, then P)
    float* Ks  = sm + AQ * KSTR;            // [2][64][68]
    float* Vs  = Ks + 2 * KT * KSTR;        // 64 x 72

    const int tid  = threadIdx.x;
    const int lane = tid & 31;
    const int warp = tid >> 5;
    const int lr   = lane >> 2;
    const int lc   = lane & 3;

    const int q0 = blockIdx.x * AQ;
    const int bh = blockIdx.y;
    const int b  = bh >> 4;
    const int h  = bh & 15;

    const float* Qb = Q + (size_t)bh * TQ * HDIM;
    const float* Kb = K + (size_t)bh * TK * HDIM;
    const float* Vb = V + (size_t)bh * TK * HDIM;

    // stage Q tile via cp.async (raw tf32 bits, pre-scaled)
#pragma unroll
    for (int r = 0; r < 8; r++) {
        int id = tid + r * 128;             // 1024 slots: 64 rows x 16 float4
        int row = id >> 4, c4 = (id & 15) * 4;
        cp16(&QPs[row * KSTR + c4], &Qb[(size_t)(q0 + row) * HDIM + c4]);
    }
    asm volatile("cp.async.commit_group;");

    auto cp_K = [&](int st, int kt) {
        const int k0 = kt * KT;
#pragma unroll
        for (int r = 0; r < 8; r++) {
            int id = tid + r * 128;
            int row = id >> 4, c4 = (id & 15) * 4;
            cp16(&Ks[st * KT * KSTR + row * KSTR + c4],
                 &Kb[(size_t)(k0 + row) * HDIM + c4]);
        }
        asm volatile("cp.async.commit_group;");
    };
    auto cp_V = [&](int kt) {
        const int k0 = kt * KT;
#pragma unroll
        for (int r = 0; r < 8; r++) {
            int id = tid + r * 128;
            int row = id >> 4, c4 = (id & 15) * 4;
            cp16(&Vs[row * VSTR + c4], &Vb[(size_t)(k0 + row) * HDIM + c4]);
        }
        asm volatile("cp.async.commit_group;");
    };

    cp_K(0, 0);                              // group: Q, K0

    // wait for Q (and K0, cheap) then hoist Q fragments
    asm volatile("cp.async.wait_group 0;");
    __syncthreads();

    unsigned qf[8][4];
#pragma unroll
    for (int kk = 0; kk < 8; kk++) {
        const float* p = &QPs[(warp * 16 + lr) * KSTR + kk * 8 + lc];
        qf[kk][0] = __float_as_uint(p[0]);
        qf[kk][1] = __float_as_uint(p[8 * KSTR]);
        qf[kk][2] = __float_as_uint(p[4]);
        qf[kk][3] = __float_as_uint(p[8 * KSTR + 4]);
    }
    __syncthreads();                         // QPs free for P scratch

    float m_i[2] = {-INFINITY, -INFINITY};
    float l_i[2] = {0.f, 0.f};
    float o[8][4];
#pragma unroll
    for (int nf = 0; nf < 8; nf++)
#pragma unroll
        for (int c = 0; c < 4; c++) o[nf][c] = 0.f;

    const int NT = TK / KT;   // 32
    for (int kt = 0; kt < NT; kt++) {
        const int k0 = kt * KT;

        cp_V(kt);                            // overlaps with QK + softmax
        if (kt + 1 < NT) cp_K((kt + 1) & 1, kt + 1);

        // K(kt) must be complete: pending groups = V(kt) [, K(kt+1)]
        if (kt + 1 < NT) asm volatile("cp.async.wait_group 2;");
        else             asm volatile("cp.async.wait_group 1;");
        __syncthreads();

        const float* Kst = &Ks[(kt & 1) * KT * KSTR];

        // S = Q @ K^T
        float s[8][4];
#pragma unroll
        for (int nf = 0; nf < 8; nf++)
#pragma unroll
            for (int c = 0; c < 4; c++) s[nf][c] = 0.f;

#pragma unroll
        for (int kk = 0; kk < 8; kk++) {
#pragma unroll
            for (int nf = 0; nf < 8; nf++) {
                unsigned bf[2];
                const float* p = &Kst[(nf * 8 + lr) * KSTR + kk * 8 + lc];
                bf[0] = __float_as_uint(p[0]);
                bf[1] = __float_as_uint(p[4]);
                mma_tf32(s[nf], qf[kk], bf);
            }
        }

        // masks + online softmax
        uchar2 kp[8];
#pragma unroll
        for (int nf = 0; nf < 8; nf++)
            kp[nf] = *(const uchar2*)&kpm[(size_t)b * TK + k0 + nf * 8 + 2 * lc];

#pragma unroll
        for (int half = 0; half < 2; half++) {
            const int qg = q0 + warp * 16 + lr + half * 8;
            const float* mrow = &mask[(size_t)qg * TK + k0];
            float mx = -INFINITY;
#pragma unroll
            for (int nf = 0; nf < 8; nf++) {
                float2 mv = *(const float2*)&mrow[nf * 8 + 2 * lc];
                float v0 = s[nf][half * 2]     + mv.x;
                float v1 = s[nf][half * 2 + 1] + mv.y;
                if (kp[nf].x) v0 = -INFINITY;
                if (kp[nf].y) v1 = -INFINITY;
                s[nf][half * 2]     = v0;
                s[nf][half * 2 + 1] = v1;
                mx = fmaxf(mx, fmaxf(v0, v1));
            }
            mx = fmaxf(mx, __shfl_xor_sync(0xffffffffu, mx, 1));
            mx = fmaxf(mx, __shfl_xor_sync(0xffffffffu, mx, 2));
            float mnew = fmaxf(m_i[half], mx);
            float alpha, rs = 0.f;
            if (mnew == -INFINITY) {
                alpha = 1.f;
#pragma unroll
                for (int nf = 0; nf < 8; nf++) {
                    s[nf][half * 2] = 0.f;
                    s[nf][half * 2 + 1] = 0.f;
                }
            } else {
                alpha = (m_i[half] == -INFINITY) ? 0.f : __expf(m_i[half] - mnew);
#pragma unroll
                for (int nf = 0; nf < 8; nf++) {
                    float p0 = __expf(s[nf][half * 2]     - mnew);
                    float p1 = __expf(s[nf][half * 2 + 1] - mnew);
                    s[nf][half * 2]     = p0;
                    s[nf][half * 2 + 1] = p1;
                    rs += p0 + p1;
                }
            }
            rs += __shfl_xor_sync(0xffffffffu, rs, 1);
            rs += __shfl_xor_sync(0xffffffffu, rs, 2);
            l_i[half] = l_i[half] * alpha + rs;
            m_i[half] = mnew;
#pragma unroll
            for (int nf = 0; nf < 8; nf++) {
                o[nf][half * 2]     *= alpha;
                o[nf][half * 2 + 1] *= alpha;
            }
        }

        // V(kt) must be complete: pending = [K(kt+1)]
        if (kt + 1 < NT) asm volatile("cp.async.wait_group 1;");
        else             asm volatile("cp.async.wait_group 0;");
        __syncthreads();

        // stage P (tf32 bits) into warp-private rows of QPs
#pragma unroll
        for (int half = 0; half < 2; half++) {
            const int row = warp * 16 + lr + half * 8;
#pragma unroll
            for (int nf = 0; nf < 8; nf++) {
                float2 pv;
                pv.x = __uint_as_float(f2tf(s[nf][half * 2]));
                pv.y = __uint_as_float(f2tf(s[nf][half * 2 + 1]));
                *(float2*)&QPs[row * KSTR + nf * 8 + 2 * lc] = pv;
            }
        }
        __syncwarp();

        // O += P @ V
#pragma unroll
        for (int kk = 0; kk < 8; kk++) {
            unsigned af[4];
            const float* pa = &QPs[(warp * 16 + lr) * KSTR + kk * 8 + lc];
            af[0] = __float_as_uint(pa[0]);
            af[1] = __float_as_uint(pa[8 * KSTR]);
            af[2] = __float_as_uint(pa[4]);
            af[3] = __float_as_uint(pa[8 * KSTR + 4]);
#pragma unroll
            for (int nf = 0; nf < 8; nf++) {
                unsigned bf[2];
                const float* pb = &Vs[(kk * 8 + lc) * VSTR + nf * 8 + lr];
                bf[0] = __float_as_uint(pb[0]);
                bf[1] = __float_as_uint(pb[4 * VSTR]);
                mma_tf32(o[nf], af, bf);
            }
        }
        __syncthreads();   // PV done before next iter's cp_V overwrites Vs
    }

    // finalize: (b, t, dmodel) layout
#pragma unroll
    for (int half = 0; half < 2; half++) {
        const float inv = (l_i[half] > 0.f) ? (1.f / l_i[half]) : 0.f;
        const int t = q0 + warp * 16 + lr + half * 8;
#pragma unroll
        for (int nf = 0; nf < 8; nf++) {
            float2 v = make_float2(o[nf][half * 2] * inv, o[nf][half * 2 + 1] * inv);
            *(float2*)&O[((size_t)(b * TQ + t)) * DMODEL + h * HDIM + nf * 8 + 2 * lc] = v;
        }
    }
}

// ---------------- launch ------------------------------------------------------
extern "C" void kernel_launch(void* const* d_in, const int* in_sizes, int n_in,
                              void* d_out, int out_size)
{
    const float* x_q   = (const float*)d_in[0];
    const float* x_kv  = (const float*)d_in[1];
    const float* amask = (const float*)d_in[2];
    const unsigned char* kpm = (const unsigned char*)d_in[3];
    const float* Wq = (const float*)d_in[4];
    const float* Wk = (const float*)d_in[5];
    const float* Wv = (const float*)d_in[6];
    const float* Wo = (const float*)d_in[7];
    float* out = (float*)d_out;

    float *qP, *kP, *vP, *oP;
    cudaGetSymbolAddress((void**)&qP, g_Q);
    cudaGetSymbolAddress((void**)&kP, g_K);
    cudaGetSymbolAddress((void**)&vP, g_V);
    cudaGetSymbolAddress((void**)&oP, g_O);

    const int gemm_smem = 2 * (BM + BN) * SSTR * (int)sizeof(float);   // 73728
    cudaFuncSetAttribute(gemm_tf32<0>, cudaFuncAttributeMaxDynamicSharedMemorySize, gemm_smem);
    cudaFuncSetAttribute(gemm_tf32<1>, cudaFuncAttributeMaxDynamicSharedMemorySize, gemm_smem);

    dim3 gblk(DMODEL / BN, MROWS / BM);   // (8, 64)
    gemm_tf32<1><<<gblk, 256, gemm_smem>>>(x_q,  Wq, qP, 0.125f);
    gemm_tf32<1><<<gblk, 256, gemm_smem>>>(x_kv, Wk, kP, 1.0f);
    gemm_tf32<1><<<gblk, 256, gemm_smem>>>(x_kv, Wv, vP, 1.0f);

    const int attn_smem = (AQ * KSTR + 2 * KT * KSTR + KT * VSTR) * (int)sizeof(float); // 70656
    cudaFuncSetAttribute(attn_tf32, cudaFuncAttributeMaxDynamicSharedMemorySize, attn_smem);
    dim3 ga(TQ / AQ, BATCH * NHEADS);     // (32, 64)
    attn_tf32<<<ga, 128, attn_smem>>>(qP, kP, vP, amask, kpm, oP);

    gemm_tf32<0><<<gblk, 256, gemm_smem>>>(oP, Wo, out, 1.0f);
}